// round 7
// baseline (speedup 1.0000x reference)
#include <cuda_runtime.h>
#include <cuda_bf16.h>
#include <cstdint>

// ContinuousEmbedding: out[b,f,:] = sum_k weight[k,:] / (|idx(x[b,f]) - k| + 1)
// Collapses to a 64x64 lookup table T (16 KB) indexed by bucket index.
//
// R7: single fused kernel, 148 blocks x 1024 threads (1/SM). Table built ONCE
// per SM (each thread computes exactly one float4 entry; reciprocals from a
// 64-entry shared table). Fan-out = R3's best-measured shape: one 32-row tile
// per warp iter, 16 x {shfl, LDS.128, STG.128 .cs}, no bounds checks.

#define NUM_BINS 63
#define KDIM 64          // NUM_BINS + 1
#define EMB_DIM 64

__global__ void __launch_bounds__(1024, 1)
fused_embed(const float* __restrict__ x,
            const float* __restrict__ low,     // [64]; low[0]=-inf, bins=low[1..]
            const float* __restrict__ weight,  // [64*64]
            float4* __restrict__ out,
            int n_rows)
{
    __shared__ float4 sT4[KDIM * 16];          // 16 KB table (float4 view)
    __shared__ float  sb[NUM_BINS];            // bin boundaries
    __shared__ float  srecip[KDIM];            // 1/(d+1), d=0..63

    const int tid = threadIdx.x;

    // ---- tiny prolog: bins + reciprocal table -----------------------------
    if (tid < NUM_BINS) sb[tid] = __ldg(low + tid + 1);
    if (tid >= 64 && tid < 128) srecip[tid - 64] = 1.0f / (float)(tid - 63);
    __syncthreads();

    // ---- build table: thread t -> float4 entry t (r = t>>4, c = t&15) -----
    // T[r, 4c..4c+3] = sum_k w[k, 4c..4c+3] * recip(|r-k|)
    // LDG addresses: 16 distinct float4 per half-warp -> 256B coalesced,
    // L1-resident after first warp. 64 iters x 4 FMA per thread.
    {
        const int r = tid >> 4;
        const int c = tid & 15;
        const float4* w4 = reinterpret_cast<const float4*>(weight);
        float4 acc = make_float4(0.f, 0.f, 0.f, 0.f);
#pragma unroll 8
        for (int k = 0; k < KDIM; ++k) {
            int d = r - k; if (d < 0) d = -d;
            const float  s = srecip[d];
            const float4 w = __ldg(w4 + k * 16 + c);
            acc.x = fmaf(w.x, s, acc.x);
            acc.y = fmaf(w.y, s, acc.y);
            acc.z = fmaf(w.z, s, acc.z);
            acc.w = fmaf(w.w, s, acc.w);
        }
        sT4[tid] = acc;
        __syncthreads();                       // table ready
    }

    // ---- streaming fan-out: one 32-row tile per warp iteration ------------
    const int lane = tid & 31;
    const int warp = tid >> 5;                 // 0..31
    const int half = lane >> 4;                // row-within-pair
    const int part = lane & 15;                // float4 slot within a row
    const int gw = blockIdx.x * 32 + warp;
    const int nw = gridDim.x * 32;
    const int n_full = n_rows & ~31;           // full 32-row tiles

    for (int base = gw * 32; base < n_full; base += nw * 32) {
        // bucket index for row base+lane: g = #{ j : bins[j] < x }
        // arithmetic guess (bins ~ linspace(-3.1,3.1,63)) + EXACT fixup
        const float xv = __ldg(x + base + lane);
        int g = (int)floorf((xv + 3.1f) * 10.0f) + 1;
        g = max(0, min(NUM_BINS, g));
        while (g > 0 && !(xv > sb[g - 1])) --g;
        while (g < NUM_BINS && (xv > sb[g])) ++g;

#pragma unroll
        for (int j = 0; j < 16; ++j) {
            const int idx = __shfl_sync(0xffffffffu, g, 2 * j + half);
            const float4 v = sT4[(idx << 4) + part];
            __stcs(&out[(size_t)(base + 2 * j) * 16 + lane], v);
        }
    }

    // ---- remainder rows (n_rows % 32), block 0 only -----------------------
    if (blockIdx.x == 0 && n_full < n_rows) {
        for (int r = n_full + warp; r < n_rows; r += 32) {
            int gg = 0;
            if (lane == 0) {
                const float xv = __ldg(x + r);
                gg = (int)floorf((xv + 3.1f) * 10.0f) + 1;
                gg = max(0, min(NUM_BINS, gg));
                while (gg > 0 && !(xv > sb[gg - 1])) --gg;
                while (gg < NUM_BINS && (xv > sb[gg])) ++gg;
            }
            gg = __shfl_sync(0xffffffffu, gg, 0);
            if (lane < 16)
                out[(size_t)r * 16 + lane] = sT4[(gg << 4) + lane];
        }
    }
}

extern "C" void kernel_launch(void* const* d_in, const int* in_sizes, int n_in,
                              void* d_out, int out_size) {
    const float* x      = (const float*)d_in[0];   // [B*F]
    const float* low    = (const float*)d_in[1];   // [64]
    // d_in[2] = high [64] (redundant with low for the bucket computation)
    const float* weight = (const float*)d_in[3];   // [64*64]

    float4* out = (float4*)d_out;
    const int n_rows = out_size / EMB_DIM;         // 524288

    // 148 blocks x 32 warps: one block per SM, table built once per SM.
    int blocks = 148;
    int n_tiles = (n_rows + 31) / 32;
    int max_blocks = (n_tiles + 31) / 32;
    if (blocks > max_blocks) blocks = max_blocks;
    if (blocks < 1) blocks = 1;

    fused_embed<<<blocks, 1024>>>(x, low, weight, out, n_rows);
}

// round 9
// speedup vs baseline: 1.1646x; 1.1646x over previous
#include <cuda_runtime.h>
#include <cuda_bf16.h>
#include <cstdint>

// ContinuousEmbedding: out[b,f,:] = sum_k weight[k,:] / (|idx(x[b,f]) - k| + 1)
// Collapses to a 64x64 lookup table T (16 KB = 1024 float4) indexed by bucket.
//
// R9 = R8 with the build-grid bug fixed: table has 1024 float4 entries, so the
// build kernel runs EXACTLY 1024 threads (<<<8,128>>>). R8's <<<32,128>>>
// wrote 4x past g_table -> IMA.
// Fan-out: explicit 8-deep register batching (R6's per-warp win) at 40
// warps/SM occupancy (launch_bounds(256,5)), stateless blocks, LDG table
// gather via L1, one-shot 2048-block grid, PDL overlap with the build.

#define NUM_BINS 63
#define KDIM 64          // NUM_BINS + 1
#define EMB_DIM 64

__device__ float g_table[KDIM * EMB_DIM];   // 4096 floats = 1024 float4

// ---------------------------------------------------------------------------
// Kernel 1: T[r][d] = sum_k weight[k][d] / (|r-k|+1).   <<<8, 128>>>
// Thread e in [0,1024) computes float4 entry e: r = e>>4 (0..63), c = e&15.
// ---------------------------------------------------------------------------
__global__ void __launch_bounds__(128)
build_table_kernel(const float* __restrict__ weight) {
    __shared__ float srecip[KDIM];
    const int tid = threadIdx.x;
    if (tid < KDIM) srecip[tid] = 1.0f / (float)(tid + 1);
    __syncthreads();

    const int e = blockIdx.x * 128 + tid;      // float4 entry 0..1023
    const int r = e >> 4;                      // 0..63
    const int c = e & 15;                      // 0..15
    const float4* w4 = reinterpret_cast<const float4*>(weight);
    float4 acc = make_float4(0.f, 0.f, 0.f, 0.f);
#pragma unroll 8
    for (int k = 0; k < KDIM; ++k) {
        int d = r - k; if (d < 0) d = -d;      // 0..63
        const float  s = srecip[d];
        const float4 w = __ldg(w4 + k * 16 + c);
        acc.x = fmaf(w.x, s, acc.x);
        acc.y = fmaf(w.y, s, acc.y);
        acc.z = fmaf(w.z, s, acc.z);
        acc.w = fmaf(w.w, s, acc.w);
    }
    reinterpret_cast<float4*>(g_table)[e] = acc;

#if __CUDA_ARCH__ >= 900
    cudaTriggerProgrammaticLaunchCompletion();
#endif
}

// ---------------------------------------------------------------------------
// Kernel 2: one 32-row tile per warp (one-shot grid). Lane i computes the
// bucket index of row base+i; then two 8-deep batches of
// {shfl-batch -> LDG.128-batch (table via L1) -> STG.128.cs-batch}.
// ---------------------------------------------------------------------------
__global__ void __launch_bounds__(256, 5)
embed_kernel(const float* __restrict__ x,
             const float* __restrict__ low,     // [64]; low[0]=-inf, bins=low[1..]
             const float4* __restrict__ table,  // g_table as float4 (1024)
             float4* __restrict__ out,
             int n_rows)
{
    const int lane = threadIdx.x & 31;
    const int warp = threadIdx.x >> 5;
    const int half = lane >> 4;        // row-within-pair
    const int part = lane & 15;        // float4 slot within a 64-float row
    const int base = (blockIdx.x * 8 + warp) * 32;

    if (base >= n_rows) {
#if __CUDA_ARCH__ >= 900
        cudaGridDependencySynchronize();
#endif
        return;
    }

    // --- bucket index for row base+lane: g = #{ j : bins[j] < x } ---------
    // Arithmetic guess (bins ~ linspace(-3.1,3.1,63), step 0.1) + EXACT
    // fixup against the real bin values (low[g] == bins[g-1]).
    int g = 0;
    if (base + lane < n_rows) {
        const float xv = __ldg(x + base + lane);
        g = (int)floorf((xv + 3.1f) * 10.0f) + 1;
        g = max(0, min(NUM_BINS, g));
        while (g > 0 && !(xv > __ldg(low + g))) --g;
        while (g < NUM_BINS && (xv > __ldg(low + g + 1))) ++g;
    }

#if __CUDA_ARCH__ >= 900
    cudaGridDependencySynchronize();   // table must be ready past this point
#endif

    const bool full = (base + 32 <= n_rows);   // uniform within warp
#pragma unroll
    for (int h = 0; h < 2; ++h) {
        int    idxs[8];
        float4 v[8];
#pragma unroll
        for (int j = 0; j < 8; ++j)
            idxs[j] = __shfl_sync(0xffffffffu, g, (h * 8 + j) * 2 + half);
#pragma unroll
        for (int j = 0; j < 8; ++j)
            v[j] = __ldg(&table[(idxs[j] << 4) + part]);
        if (full) {
#pragma unroll
            for (int j = 0; j < 8; ++j)
                __stcs(&out[(size_t)(base + (h * 8 + j) * 2) * 16 + lane], v[j]);
        } else {
#pragma unroll
            for (int j = 0; j < 8; ++j) {
                const int r = base + (h * 8 + j) * 2 + half;
                if (r < n_rows)
                    __stcs(&out[(size_t)r * 16 + part], v[j]);
            }
        }
    }
}

extern "C" void kernel_launch(void* const* d_in, const int* in_sizes, int n_in,
                              void* d_out, int out_size) {
    const float* x      = (const float*)d_in[0];   // [B*F]
    const float* low    = (const float*)d_in[1];   // [64]
    // d_in[2] = high [64] (redundant with low for the bucket computation)
    const float* weight = (const float*)d_in[3];   // [64*64]

    float4* out = (float4*)d_out;
    const int n_rows = out_size / EMB_DIM;         // 524288

    build_table_kernel<<<8, 128>>>(weight);        // exactly 1024 threads

    float4* table4 = nullptr;
    cudaGetSymbolAddress((void**)&table4, g_table);

    // 2048 blocks x 8 warps x 32 rows = 524288 rows exactly (one-shot).
    int blocks = (n_rows + 255) / 256;
    if (blocks < 1) blocks = 1;

    cudaLaunchConfig_t cfg = {};
    cfg.gridDim  = dim3((unsigned)blocks, 1, 1);
    cfg.blockDim = dim3(256, 1, 1);
    cfg.dynamicSmemBytes = 0;
    cfg.stream = 0;
    cudaLaunchAttribute attr[1];
    attr[0].id = cudaLaunchAttributeProgrammaticStreamSerialization;
    attr[0].val.programmaticStreamSerializationAllowed = 1;
    cfg.attrs = attr;
    cfg.numAttrs = 1;

    cudaError_t e = cudaLaunchKernelEx(&cfg, embed_kernel,
                                       x, low, (const float4*)table4, out, n_rows);
    if (e != cudaSuccess) {
        embed_kernel<<<blocks, 256>>>(x, low, (const float4*)table4, out, n_rows);
    }
}

// round 10
// speedup vs baseline: 1.1659x; 1.0011x over previous
#include <cuda_runtime.h>
#include <cuda_bf16.h>
#include <cstdint>

// ContinuousEmbedding: out[b,f,:] = sum_k weight[k,:] / (|idx(x[b,f]) - k| + 1)
// Collapses to a 64x64 lookup table T (16 KB = 1024 float4) indexed by bucket.
//
// R10: ONE kernel. Blocks 0..3 build the table (1 float4 entry per thread);
// every block overlaps its x-load + bucket fixup with the build, then spins
// on an acquire-loaded ready counter before the gather. Self-resetting
// done-counter protocol -> identical work every launch (graph-safe).
// Fan-out = R9's measured-best shape: 8-deep register-batched
// {shfl -> LDG.128 table -> STG.128.cs}, launch_bounds(256,5).

#define NUM_BINS 63
#define KDIM 64          // NUM_BINS + 1
#define EMB_DIM 64
#define NBUILD 4         // builder blocks (4 x 256 = 1024 float4 entries)

__device__ float g_table[KDIM * EMB_DIM];   // 4096 floats = 1024 float4
__device__ int   g_ready;                   // builders done (0..NBUILD)
__device__ int   g_done;                    // blocks finished (for reset)

__global__ void __launch_bounds__(256, 5)
embed_fused(const float* __restrict__ x,
            const float* __restrict__ low,     // [64]; low[0]=-inf, bins=low[1..]
            const float* __restrict__ weight,  // [64*64]
            float4* __restrict__ out,
            int n_rows)
{
    const int tid = threadIdx.x;
    const int bid = blockIdx.x;

    // ---- phase 1a: builder blocks compute their 256 table entries --------
    if (bid < NBUILD) {
        __shared__ float srecip[KDIM];
        if (tid < KDIM) srecip[tid] = 1.0f / (float)(tid + 1);
        __syncthreads();

        const int e = bid * 256 + tid;         // float4 entry 0..1023
        const int r = e >> 4;                  // 0..63
        const int c = e & 15;                  // 0..15
        const float4* w4 = reinterpret_cast<const float4*>(weight);
        float4 acc = make_float4(0.f, 0.f, 0.f, 0.f);
#pragma unroll 16
        for (int k = 0; k < KDIM; ++k) {
            int d = r - k; if (d < 0) d = -d;
            const float  s = srecip[d];
            const float4 w = __ldg(w4 + k * 16 + c);
            acc.x = fmaf(w.x, s, acc.x);
            acc.y = fmaf(w.y, s, acc.y);
            acc.z = fmaf(w.z, s, acc.z);
            acc.w = fmaf(w.w, s, acc.w);
        }
        reinterpret_cast<float4*>(g_table)[e] = acc;
        __threadfence();                       // table writes visible (gpu scope)
        __syncthreads();
        if (tid == 0) atomicAdd(&g_ready, 1);
    }

    // ---- phase 1b (all blocks): bucket index, overlapped with build ------
    const int lane = tid & 31;
    const int warp = tid >> 5;
    const int half = lane >> 4;        // row-within-pair
    const int part = lane & 15;        // float4 slot within a 64-float row
    const int base = (bid * 8 + warp) * 32;
    const bool active = (base < n_rows);

    // g = #{ j : bins[j] < x }: arithmetic guess (bins ~ linspace(-3.1,3.1))
    // then EXACT fixup against the real bin values (low[g] == bins[g-1]).
    int g = 0;
    if (active && base + lane < n_rows) {
        const float xv = __ldg(x + base + lane);
        g = (int)floorf((xv + 3.1f) * 10.0f) + 1;
        g = max(0, min(NUM_BINS, g));
        while (g > 0 && !(xv > __ldg(low + g))) --g;
        while (g < NUM_BINS && (xv > __ldg(low + g + 1))) ++g;
    }

    // ---- phase 2: wait for the table ---------------------------------------
    if (tid == 0) {
        int r;
        do {
            asm volatile("ld.global.acquire.gpu.b32 %0, [%1];"
                         : "=r"(r) : "l"(&g_ready) : "memory");
        } while (r < NBUILD);
    }
    __syncthreads();

    // ---- phase 3: fan-out (R9 shape) ---------------------------------------
    if (active) {
        const float4* table = reinterpret_cast<const float4*>(g_table);
        const bool full = (base + 32 <= n_rows);   // uniform within warp
#pragma unroll
        for (int h = 0; h < 2; ++h) {
            int    idxs[8];
            float4 v[8];
#pragma unroll
            for (int j = 0; j < 8; ++j)
                idxs[j] = __shfl_sync(0xffffffffu, g, (h * 8 + j) * 2 + half);
#pragma unroll
            for (int j = 0; j < 8; ++j)
                v[j] = __ldg(&table[(idxs[j] << 4) + part]);
            if (full) {
#pragma unroll
                for (int j = 0; j < 8; ++j)
                    __stcs(&out[(size_t)(base + (h * 8 + j) * 2) * 16 + lane], v[j]);
            } else {
#pragma unroll
                for (int j = 0; j < 8; ++j) {
                    const int r = base + (h * 8 + j) * 2 + half;
                    if (r < n_rows)
                        __stcs(&out[(size_t)r * 16 + part], v[j]);
                }
            }
        }
    }

    // ---- phase 4: self-reset so every launch is identical ------------------
    __syncthreads();
    if (tid == 0) {
        const int prev = atomicAdd(&g_done, 1);
        if (prev == (int)gridDim.x - 1) {      // last block: reset protocol
            atomicExch(&g_done, 0);
            atomicExch(&g_ready, 0);
        }
    }
}

extern "C" void kernel_launch(void* const* d_in, const int* in_sizes, int n_in,
                              void* d_out, int out_size) {
    const float* x      = (const float*)d_in[0];   // [B*F]
    const float* low    = (const float*)d_in[1];   // [64]
    // d_in[2] = high [64] (redundant with low for the bucket computation)
    const float* weight = (const float*)d_in[3];   // [64*64]

    float4* out = (float4*)d_out;
    const int n_rows = out_size / EMB_DIM;         // 524288

    // One-shot grid: 8 warps x 32 rows per block. At least NBUILD blocks.
    int blocks = (n_rows + 255) / 256;             // 2048 for the real shape
    if (blocks < NBUILD) blocks = NBUILD;

    embed_fused<<<blocks, 256>>>(x, low, weight, out, n_rows);
}